// round 13
// baseline (speedup 1.0000x reference)
#include <cuda_runtime.h>
#include <math.h>

#define BB 4
#define HH 48
#define WW 48
#define LL (HH*WW)      /* 2304 */
#define DM 96
#define DI 192
#define NS 16
#define RR 6
#define KK 3
#define XD 32           /* row: [B0..B15, C0..C15] */
#define CH (BB*KK*DI)   /* 2304 chains */
#define SS 48           /* scan segments */
#define LSEG (LL/SS)    /* 48 */
#define TT 16           /* spatial tokens per k_mid block */

typedef unsigned long long u64;
union F2U { float2 f; u64 u; };
union F4U { float4 f; u64 u[2]; };

__device__ __forceinline__ u64 F2P(float x, float y){ F2U t; t.f=make_float2(x,y); return t.u; }
__device__ __forceinline__ float LOF(u64 v){ F2U t; t.u=v; return t.f.x; }
__device__ __forceinline__ float HIF(u64 v){ F2U t; t.u=v; return t.f.y; }
__device__ __forceinline__ u64 fma2(u64 a,u64 b,u64 c){ u64 d; asm("fma.rn.f32x2 %0,%1,%2,%3;":"=l"(d):"l"(a),"l"(b),"l"(c)); return d; }
__device__ __forceinline__ u64 mul2(u64 a,u64 b){ u64 d; asm("mul.rn.f32x2 %0,%1,%2;":"=l"(d):"l"(a),"l"(b)); return d; }

/* ---------------- scratch ---------------- */
__device__ float  g_xcraw[BB*LL*DI];
__device__ float  g_z    [BB*LL*DI];
__device__ float  g_xch  [BB*LL*DI];
__device__ float  g_xdbl [BB*KK*LL*XD];
__device__ float2 g_pre  [(size_t)BB*KK*LL*DI];   /* {e1, dt*u}  [bk][l][d] */
__device__ float  g_segq [SS][NS][CH];
__device__ float  g_segp [SS][CH];
__device__ float  g_hin  [SS][NS][CH];
__device__ float  g_ys   [KK][BB*LL*DI];

__device__ __forceinline__ float fsilu(float v){ return v / (1.f + __expf(-v)); }

/* ------------- in_proj ------------- */
__global__ void k_inproj(const float* __restrict__ x, const float* __restrict__ w)
{
    __shared__ float xt[16*DM];
    int tb = blockIdx.x * 16;
    for (int i=threadIdx.x;i<16*DM;i+=blockDim.x) xt[i]=x[(size_t)tb*DM+i];
    __syncthreads();
    int j = threadIdx.x;
    u64 acc[16];
#pragma unroll
    for(int t=0;t<16;t++) acc[t]=0ull;
    const float4* w4 = reinterpret_cast<const float4*>(w + j*DM);
#pragma unroll
    for(int c4=0;c4<DM/4;c4++){
        F4U wv; wv.f = w4[c4];
#pragma unroll
        for(int t=0;t<16;t++){
            F4U xv; xv.f = *reinterpret_cast<const float4*>(&xt[t*DM+c4*4]);
            acc[t]=fma2(wv.u[0],xv.u[0],acc[t]);
            acc[t]=fma2(wv.u[1],xv.u[1],acc[t]);
        }
    }
    if(j<DI){
#pragma unroll
        for(int t=0;t<16;t++) g_xcraw[(size_t)(tb+t)*DI+j]=LOF(acc[t])+HIF(acc[t]);
    } else {
        int jz=j-DI;
#pragma unroll
        for(int t=0;t<16;t++) g_z[(size_t)(tb+t)*DI+jz]=fsilu(LOF(acc[t])+HIF(acc[t]));
    }
}

/* ------------- fused conv + x_proj + dt_proj + delta (TT=16 tile) ------------- */
__global__ __launch_bounds__(256) void k_mid(
    const float* __restrict__ cw, const float* __restrict__ cb,
    const float* __restrict__ xw,
    const float* __restrict__ dtw_g, const float* __restrict__ dtb_g,
    const float* __restrict__ alog)
{
    __shared__ float sxc[TT*DI];
    __shared__ float stage[KK*TT][40];
    int b  = blockIdx.y;
    int l0 = blockIdx.x * TT;
    int tid = threadIdx.x;

    if (tid < DI){
        int d = tid;
        float wt[9];
#pragma unroll
        for(int i=0;i<9;i++) wt[i]=cw[d*9+i];
        float bias=cb[d];
        const float* base = g_xcraw + (size_t)b*LL*DI + d;
        float* xo = g_xch + ((size_t)b*LL + l0)*DI + d;
#pragma unroll 4
        for(int t=0;t<TT;t++){
            int l=l0+t, h=l/WW, w0=l%WW;
            float s=bias;
#pragma unroll
            for(int kh=0;kh<3;kh++){
                int h2=h+kh-1;
                if((unsigned)h2>=HH) continue;
#pragma unroll
                for(int kw=0;kw<3;kw++){
                    int w2=w0+kw-1;
                    if((unsigned)w2>=WW) continue;
                    s += base[(size_t)(h2*WW+w2)*DI]*wt[kh*3+kw];
                }
            }
            float v=fsilu(s);
            sxc[t*DI+d]=v;
            xo[(size_t)t*DI]=v;
        }
    }
    __syncthreads();

    if (tid < 228){
        int j = tid % 114;
        int t0 = (tid >= 114) ? 8 : 0;
        int k = j/38, c = j%38;
        u64 acc[8];
#pragma unroll
        for(int t=0;t<8;t++) acc[t]=0ull;
        const float4* w4 = reinterpret_cast<const float4*>(xw + (size_t)(k*38+c)*DI);
        for(int d4=0; d4<DI/4; d4++){
            F4U wv; wv.f=w4[d4];
#pragma unroll
            for(int t=0;t<8;t++){
                F4U xv; xv.f=*reinterpret_cast<const float4*>(&sxc[(t0+t)*DI+d4*4]);
                acc[t]=fma2(wv.u[0],xv.u[0],acc[t]);
                acc[t]=fma2(wv.u[1],xv.u[1],acc[t]);
            }
        }
        int slot = (c<RR)? c : (c<RR+NS ? 8+(c-RR) : 24+(c-RR-NS));
#pragma unroll
        for(int t=0;t<8;t++) stage[k*TT+t0+t][slot]=LOF(acc[t])+HIF(acc[t]);
    }
    __syncthreads();

    if (tid < DI){
        int d = tid;
#pragma unroll
        for(int k=0;k<KK;k++){
            float dtw[RR];
#pragma unroll
            for(int r=0;r<RR;r++) dtw[r]=dtw_g[(size_t)(k*DI+d)*RR+r];
            float bias=dtb_g[k*DI+d];
            float A0 = -__expf(alog[(size_t)(k*DI+d)*NS]);
            float2* pb = g_pre + ((size_t)(b*KK+k)*LL)*DI + d;
#pragma unroll 4
            for(int t=0;t<TT;t++){
                int lsp=l0+t;
                int p = (k==0)? lsp : (k==1 ? (lsp%WW)*HH + lsp/WW : LL-1-lsp);
                float s=bias;
#pragma unroll
                for(int r=0;r<RR;r++) s += dtw[r]*stage[k*TT+t][r];
                float dt = fmaxf(s,0.f) + __logf(1.f + __expf(-fabsf(s)));
                float e1 = __expf(dt * A0);
                pb[(size_t)p*DI] = make_float2(e1, dt*sxc[t*DI+d]);
            }
        }
    }

    for(int i=tid; i<KK*TT*XD; i+=256){
        int row=i/XD, j=i%XD;
        int k=row/TT, t=row%TT;
        int lsp=l0+t;
        int p = (k==0)? lsp : (k==1 ? (lsp%WW)*HH + lsp/WW : LL-1-lsp);
        g_xdbl[((size_t)(b*KK+k)*LL+p)*XD + j] = stage[row][8+j];
    }
}

/* decay powers for 4 state-pairs of group g: a[j]=(e1^(8g+2j+1), e1^(8g+2j+2)) */
__device__ __forceinline__ void tree_pow4(float e1, float m, u64 a[4]){
    float e2=e1*e1, e4=e2*e2;
    u64 e2p=F2P(e2,e2), e4p=F2P(e4,e4);
    a[0]=F2P(e1*m, e2*m);
    a[1]=mul2(a[0],e2p);
    a[2]=mul2(a[0],e4p);
    a[3]=mul2(a[1],e4p);
}

/* ------------- scan pass 1: segment summaries, h0=0 (2 threads/chain) ------------- */
__global__ __launch_bounds__(384, 4) void k_scan1(const float* __restrict__ alog)
{
    __shared__ float sb[LSEG*32];
    int seg = blockIdx.x, bk = blockIdx.y;
    int tid = threadIdx.x;
    int d = tid >> 1, g = tid & 1;
    int chain = bk*DI + d;
    int k = bk % KK;
    int l0 = seg*LSEG;
    {
        const float4* src = reinterpret_cast<const float4*>(g_xdbl + ((size_t)bk*LL + l0)*XD);
        for(int i=tid;i<LSEG*8;i+=384)
            reinterpret_cast<float4*>(sb)[i]=src[i];
    }
    __syncthreads();

    const float* ar = alog + (size_t)(k*DI+d)*NS;
    float a0 = ar[0];
    bool unit=true;
#pragma unroll
    for(int n=0;n<NS;n++){
        float r=__expf(ar[n]-a0);
        unit = unit && (fabsf(r-(float)(n+1))<1e-3f);
    }
    bool wunit = __all_sync(0xffffffffu, unit);
    const float2* pre = g_pre + (size_t)bk*LL*DI + d;
    float pe=1.f;
    if(wunit){
        u64 h2[4];
#pragma unroll
        for(int j=0;j<4;j++) h2[j]=0ull;
        float2 c0=pre[(size_t)l0*DI], c1=pre[(size_t)(l0+1)*DI];
        for(int io=0;io<LSEG;io+=2){
            float2 n0=c0, n1=c1;
            if(io+2<LSEG){ n0=pre[(size_t)(l0+io+2)*DI]; n1=pre[(size_t)(l0+io+3)*DI]; }
#pragma unroll
            for(int half=0; half<2; half++){
                float2 ed = half? c1 : c0;
                int i = io + half;
                pe *= ed.x;
                float e2=ed.x*ed.x, e4=e2*e2, e8=e4*e4;
                float m = g ? e8 : 1.f;
                u64 a[4]; tree_pow4(ed.x, m, a);
                u64 du2=F2P(ed.y,ed.y);
                F4U bv0=*reinterpret_cast<const F4U*>(&sb[i*32+8*g]);
                F4U bv1=*reinterpret_cast<const F4U*>(&sb[i*32+8*g+4]);
                h2[0]=fma2(a[0],h2[0],mul2(du2,bv0.u[0]));
                h2[1]=fma2(a[1],h2[1],mul2(du2,bv0.u[1]));
                h2[2]=fma2(a[2],h2[2],mul2(du2,bv1.u[0]));
                h2[3]=fma2(a[3],h2[3],mul2(du2,bv1.u[1]));
            }
            c0=n0; c1=n1;
        }
#pragma unroll
        for(int j=0;j<4;j++){
            g_segq[seg][8*g+2*j][chain]  =LOF(h2[j]);
            g_segq[seg][8*g+2*j+1][chain]=HIF(h2[j]);
        }
    } else {
        float rn[8], h[8];
#pragma unroll
        for(int jj=0;jj<8;jj++){ rn[jj]=__expf(ar[8*g+jj]-a0); h[jj]=0.f; }
        for(int i=0;i<LSEG;i++){
            float2 ed=pre[(size_t)(l0+i)*DI];
            pe*=ed.x;
            float lg=__log2f(ed.x), du=ed.y;
#pragma unroll
            for(int jj=0;jj<8;jj++)
                h[jj]=exp2f(lg*rn[jj])*h[jj] + du*sb[i*32+8*g+jj];
        }
#pragma unroll
        for(int jj=0;jj<8;jj++) g_segq[seg][8*g+jj][chain]=h[jj];
    }
    if(g==0) g_segp[seg][chain]=pe;
}

/* ------------- combine: two-level parallel prefix (8 threads x 6 segments) ------------- */
__global__ __launch_bounds__(256) void k_comb(const float* __restrict__ alog)
{
    int gt = blockIdx.x*256 + threadIdx.x;   /* CH*NS*8 threads */
    int t  = gt & 7;
    int cn = gt >> 3;
    int chain = cn % CH;
    int n  = cn / CH;
    int d = chain % DI, k = (chain / DI) % KK;
    const float* ar = alog + (size_t)(k*DI+d)*NS;
    float ratio = __expf(ar[n] - ar[0]);
    float rf = rintf(ratio);
    int   m  = (int)rf;
    bool exact = (fabsf(ratio-rf) < 1e-3f) && m >= 1 && m <= 31;
    int s0 = t*6;                            /* 48 = 8 x 6 */
    float A=1.f, Q=0.f;
    float Ap[6], Qp[6];
#pragma unroll
    for(int i=0;i<6;i++){
        Ap[i]=A; Qp[i]=Q;
        float pe = __ldg(&g_segp[s0+i][chain]);
        float q  = __ldg(&g_segq[s0+i][n][chain]);
        float a;
        if (exact){
            float pe2=pe*pe, pe4=pe2*pe2, pe8=pe4*pe4, pe16=pe8*pe8;
            a = (m&1)? pe : 1.f;
            if(m&2)  a*=pe2;
            if(m&4)  a*=pe4;
            if(m&8)  a*=pe8;
            if(m&16) a*=pe16;
        } else {
            a = exp2f(__log2f(pe)*ratio);
        }
        A = a*A;
        Q = a*Q + q;
    }
#pragma unroll
    for(int dlt=1; dlt<8; dlt<<=1){
        float Apv = __shfl_up_sync(0xffffffffu, A, dlt, 8);
        float Qpv = __shfl_up_sync(0xffffffffu, Q, dlt, 8);
        if (t >= dlt){ Q = A*Qpv + Q; A = A*Apv; }
    }
    float hin = __shfl_up_sync(0xffffffffu, Q, 1, 8);
    if (t == 0) hin = 0.f;
#pragma unroll
    for(int i=0;i<6;i++)
        g_hin[s0+i][n][chain] = Ap[i]*hin + Qp[i];
}

/* ------------- scan pass 2: rescan with h_init, emit y (2 threads/chain) ------------- */
__global__ __launch_bounds__(384, 4) void k_scan2(const float* __restrict__ alog)
{
    __shared__ float sb[LSEG*32];
    int seg=blockIdx.x, bk=blockIdx.y;
    int tid=threadIdx.x;
    int d = tid >> 1, g = tid & 1;
    int chain=bk*DI+d;
    int k=bk%KK, b=bk/KK;
    int l0=seg*LSEG;
    {
        const float4* src = reinterpret_cast<const float4*>(g_xdbl + ((size_t)bk*LL + l0)*XD);
        for(int i=tid;i<LSEG*8;i+=384)
            reinterpret_cast<float4*>(sb)[i]=src[i];
    }
    __syncthreads();
    const float* ar=alog+(size_t)(k*DI+d)*NS;
    float a0=ar[0];
    bool unit=true;
#pragma unroll
    for(int n=0;n<NS;n++){ float r=__expf(ar[n]-a0); unit=unit&&(fabsf(r-(float)(n+1))<1e-3f); }
    bool wunit=__all_sync(0xffffffffu,unit);
    const float2* pre=g_pre+(size_t)bk*LL*DI+d;
    float* yout=g_ys[k]+(size_t)b*LL*DI+d;
    int hh=l0%HH, wc=l0/HH;
    if(wunit){
        u64 h2[4];
#pragma unroll
        for(int j=0;j<4;j++) h2[j]=F2P(g_hin[seg][8*g+2*j][chain], g_hin[seg][8*g+2*j+1][chain]);
        float2 c0=pre[(size_t)l0*DI], c1=pre[(size_t)(l0+1)*DI];
        for(int io=0;io<LSEG;io+=2){
            float2 n0=c0, n1=c1;
            if(io+2<LSEG){ n0=pre[(size_t)(l0+io+2)*DI]; n1=pre[(size_t)(l0+io+3)*DI]; }
#pragma unroll
            for(int half=0; half<2; half++){
                float2 ed = half? c1 : c0;
                int i = io + half;
                float e2=ed.x*ed.x, e4=e2*e2, e8=e4*e4;
                float m = g ? e8 : 1.f;
                u64 a[4]; tree_pow4(ed.x, m, a);
                u64 du2=F2P(ed.y,ed.y);
                F4U bv0=*reinterpret_cast<const F4U*>(&sb[i*32+8*g]);
                F4U bv1=*reinterpret_cast<const F4U*>(&sb[i*32+8*g+4]);
                F4U cv0=*reinterpret_cast<const F4U*>(&sb[i*32+16+8*g]);
                F4U cv1=*reinterpret_cast<const F4U*>(&sb[i*32+16+8*g+4]);
                u64 ya=0ull, yb=0ull;
                h2[0]=fma2(a[0],h2[0],mul2(du2,bv0.u[0])); ya=fma2(h2[0],cv0.u[0],ya);
                h2[1]=fma2(a[1],h2[1],mul2(du2,bv0.u[1])); yb=fma2(h2[1],cv0.u[1],yb);
                h2[2]=fma2(a[2],h2[2],mul2(du2,bv1.u[0])); ya=fma2(h2[2],cv1.u[0],ya);
                h2[3]=fma2(a[3],h2[3],mul2(du2,bv1.u[1])); yb=fma2(h2[3],cv1.u[1],yb);
                float y=LOF(ya)+HIF(ya)+LOF(yb)+HIF(yb);
                y += __shfl_xor_sync(0xffffffffu, y, 1);
                int l=l0+i, pos;
                if(k==0) pos=l;
                else if(k==1){ pos=hh*WW+wc; hh++; if(hh==HH){hh=0;wc++;} }
                else pos=LL-1-l;
                if(g==0) yout[(size_t)pos*DI]=y;
            }
            c0=n0; c1=n1;
        }
    } else {
        float rn[8],h[8];
#pragma unroll
        for(int jj=0;jj<8;jj++){ rn[jj]=__expf(ar[8*g+jj]-a0); h[jj]=g_hin[seg][8*g+jj][chain]; }
        for(int i=0;i<LSEG;i++){
            float2 ed=pre[(size_t)(l0+i)*DI];
            float lg=__log2f(ed.x), du=ed.y, y=0.f;
#pragma unroll
            for(int jj=0;jj<8;jj++){
                h[jj]=exp2f(lg*rn[jj])*h[jj]+du*sb[i*32+8*g+jj];
                y+=h[jj]*sb[i*32+16+8*g+jj];
            }
            y += __shfl_xor_sync(0xffffffffu, y, 1);
            int l=l0+i,pos;
            if(k==0)pos=l;
            else if(k==1){pos=hh*WW+wc;hh++;if(hh==HH){hh=0;wc++;}}
            else pos=LL-1-l;
            if(g==0) yout[(size_t)pos*DI]=y;
        }
    }
}

/* ------------- merge (vectorized) + D-term + gating + out_proj ------------- */
__global__ __launch_bounds__(128) void k_out(const float* __restrict__ ow, const float* __restrict__ Ds,
                                             float* __restrict__ out)
{
    __shared__ float yz[16*DI];
    __shared__ float dsum_s[DI];
    int tid=threadIdx.x;
    int tb=blockIdx.x*16;
    size_t base4=(size_t)tb*DI/4;
    for(int i=tid;i<DI;i+=128) dsum_s[i]=Ds[i]+Ds[DI+i]+Ds[2*DI+i];
    __syncthreads();
    {
        const float4* y0=reinterpret_cast<const float4*>(g_ys[0])+base4;
        const float4* y1=reinterpret_cast<const float4*>(g_ys[1])+base4;
        const float4* y2=reinterpret_cast<const float4*>(g_ys[2])+base4;
        const float4* xc=reinterpret_cast<const float4*>(g_xch)+base4;
        const float4* zz=reinterpret_cast<const float4*>(g_z)+base4;
#pragma unroll
        for(int it=0; it<6; it++){
            int i4 = tid + it*128;
            int dd4=(i4*4)%DI;
            float4 a=y0[i4], b=y1[i4], c=y2[i4], x=xc[i4], z=zz[i4];
            float4 ds=*reinterpret_cast<const float4*>(&dsum_s[dd4]);
            float4 v;
            v.x=(a.x+b.x+c.x+ds.x*x.x)*z.x;
            v.y=(a.y+b.y+c.y+ds.y*x.y)*z.y;
            v.z=(a.z+b.z+c.z+ds.z*x.z)*z.z;
            v.w=(a.w+b.w+c.w+ds.w*x.w)*z.w;
            *reinterpret_cast<float4*>(&yz[i4*4])=v;
        }
    }
    __syncthreads();
    int j=tid;
    if(j<DM){
        u64 acc[16];
#pragma unroll
        for(int t=0;t<16;t++) acc[t]=0ull;
        const float4* w4=reinterpret_cast<const float4*>(ow+(size_t)j*DI);
        for(int d4=0;d4<DI/4;d4++){
            F4U wv; wv.f=w4[d4];
#pragma unroll
            for(int t=0;t<16;t++){
                F4U xv; xv.f=*reinterpret_cast<const float4*>(&yz[t*DI+d4*4]);
                acc[t]=fma2(wv.u[0],xv.u[0],acc[t]);
                acc[t]=fma2(wv.u[1],xv.u[1],acc[t]);
            }
        }
#pragma unroll
        for(int t=0;t<16;t++) out[(size_t)(tb+t)*DM+j]=LOF(acc[t])+HIF(acc[t]);
    }
}

/* ---------------- launcher ---------------- */
extern "C" void kernel_launch(void* const* d_in, const int* in_sizes, int n_in,
                              void* d_out, int out_size)
{
    const float* x    = (const float*)d_in[0];
    const float* inw  = (const float*)d_in[2];
    const float* cw   = (const float*)d_in[3];
    const float* cb   = (const float*)d_in[4];
    const float* xw   = (const float*)d_in[5];
    const float* dtw  = (const float*)d_in[6];
    const float* dtb  = (const float*)d_in[7];
    const float* alog = (const float*)d_in[8];
    const float* Ds   = (const float*)d_in[9];
    const float* ow   = (const float*)d_in[10];
    float* out = (float*)d_out;

    k_inproj<<<BB*LL/16, 384>>>(x, inw);
    k_mid   <<<dim3(LL/TT, BB), 256>>>(cw, cb, xw, dtw, dtb, alog);
    k_scan1 <<<dim3(SS, BB*KK), 384>>>(alog);
    k_comb  <<<CH*NS*8/256, 256>>>(alog);
    k_scan2 <<<dim3(SS, BB*KK), 384>>>(alog);
    k_out   <<<BB*LL/16, 128>>>(ow, Ds, out);
}

// round 14
// speedup vs baseline: 1.0911x; 1.0911x over previous
#include <cuda_runtime.h>
#include <math.h>

#define BB 4
#define HH 48
#define WW 48
#define LL (HH*WW)      /* 2304 */
#define DM 96
#define DI 192
#define NS 16
#define RR 6
#define KK 3
#define XD 32           /* row: [B0..B15, C0..C15] */
#define CH (BB*KK*DI)   /* 2304 chains */
#define SS 48           /* scan segments */
#define LSEG (LL/SS)    /* 48 */
#define TT 16           /* spatial tokens per k_mid block */

typedef unsigned long long u64;
union F2U { float2 f; u64 u; };
union F4U { float4 f; u64 u[2]; };

__device__ __forceinline__ u64 F2P(float x, float y){ F2U t; t.f=make_float2(x,y); return t.u; }
__device__ __forceinline__ float LOF(u64 v){ F2U t; t.u=v; return t.f.x; }
__device__ __forceinline__ float HIF(u64 v){ F2U t; t.u=v; return t.f.y; }
__device__ __forceinline__ u64 fma2(u64 a,u64 b,u64 c){ u64 d; asm("fma.rn.f32x2 %0,%1,%2,%3;":"=l"(d):"l"(a),"l"(b),"l"(c)); return d; }
__device__ __forceinline__ u64 mul2(u64 a,u64 b){ u64 d; asm("mul.rn.f32x2 %0,%1,%2;":"=l"(d):"l"(a),"l"(b)); return d; }

/* ---------------- scratch ---------------- */
__device__ float  g_xcraw[BB*LL*DI];
__device__ float  g_z    [BB*LL*DI];
__device__ float  g_xch  [BB*LL*DI];
__device__ float  g_xdbl [BB*KK*LL*XD];
__device__ float2 g_pre  [(size_t)BB*KK*LL*DI];   /* {e1, dt*u}  [bk][l][d] */
__device__ float  g_segq [SS][NS][CH];
__device__ float  g_segp [SS][CH];
__device__ float  g_hin  [SS][NS][CH];
__device__ float  g_ys   [KK][BB*LL*DI];

__device__ __forceinline__ float fsilu(float v){ return v / (1.f + __expf(-v)); }

/* ------------- in_proj ------------- */
__global__ void k_inproj(const float* __restrict__ x, const float* __restrict__ w)
{
    __shared__ float xt[16*DM];
    int tb = blockIdx.x * 16;
    for (int i=threadIdx.x;i<16*DM;i+=blockDim.x) xt[i]=x[(size_t)tb*DM+i];
    __syncthreads();
    int j = threadIdx.x;
    u64 acc[16];
#pragma unroll
    for(int t=0;t<16;t++) acc[t]=0ull;
    const float4* w4 = reinterpret_cast<const float4*>(w + j*DM);
#pragma unroll
    for(int c4=0;c4<DM/4;c4++){
        F4U wv; wv.f = w4[c4];
#pragma unroll
        for(int t=0;t<16;t++){
            F4U xv; xv.f = *reinterpret_cast<const float4*>(&xt[t*DM+c4*4]);
            acc[t]=fma2(wv.u[0],xv.u[0],acc[t]);
            acc[t]=fma2(wv.u[1],xv.u[1],acc[t]);
        }
    }
    if(j<DI){
#pragma unroll
        for(int t=0;t<16;t++) g_xcraw[(size_t)(tb+t)*DI+j]=LOF(acc[t])+HIF(acc[t]);
    } else {
        int jz=j-DI;
#pragma unroll
        for(int t=0;t<16;t++) g_z[(size_t)(tb+t)*DI+jz]=fsilu(LOF(acc[t])+HIF(acc[t]));
    }
}

/* ------------- fused conv + x_proj + dt_proj + delta (TT=16 tile) ------------- */
__global__ __launch_bounds__(256) void k_mid(
    const float* __restrict__ cw, const float* __restrict__ cb,
    const float* __restrict__ xw,
    const float* __restrict__ dtw_g, const float* __restrict__ dtb_g,
    const float* __restrict__ alog)
{
    __shared__ float sxc[TT*DI];
    __shared__ float stage[KK*TT][40];
    int b  = blockIdx.y;
    int l0 = blockIdx.x * TT;
    int tid = threadIdx.x;

    if (tid < DI){
        int d = tid;
        float wt[9];
#pragma unroll
        for(int i=0;i<9;i++) wt[i]=cw[d*9+i];
        float bias=cb[d];
        const float* base = g_xcraw + (size_t)b*LL*DI + d;
        float* xo = g_xch + ((size_t)b*LL + l0)*DI + d;
#pragma unroll 4
        for(int t=0;t<TT;t++){
            int l=l0+t, h=l/WW, w0=l%WW;
            float s=bias;
#pragma unroll
            for(int kh=0;kh<3;kh++){
                int h2=h+kh-1;
                if((unsigned)h2>=HH) continue;
#pragma unroll
                for(int kw=0;kw<3;kw++){
                    int w2=w0+kw-1;
                    if((unsigned)w2>=WW) continue;
                    s += base[(size_t)(h2*WW+w2)*DI]*wt[kh*3+kw];
                }
            }
            float v=fsilu(s);
            sxc[t*DI+d]=v;
            xo[(size_t)t*DI]=v;
        }
    }
    __syncthreads();

    if (tid < 228){
        int j = tid % 114;
        int t0 = (tid >= 114) ? 8 : 0;
        int k = j/38, c = j%38;
        u64 acc[8];
#pragma unroll
        for(int t=0;t<8;t++) acc[t]=0ull;
        const float4* w4 = reinterpret_cast<const float4*>(xw + (size_t)(k*38+c)*DI);
        for(int d4=0; d4<DI/4; d4++){
            F4U wv; wv.f=w4[d4];
#pragma unroll
            for(int t=0;t<8;t++){
                F4U xv; xv.f=*reinterpret_cast<const float4*>(&sxc[(t0+t)*DI+d4*4]);
                acc[t]=fma2(wv.u[0],xv.u[0],acc[t]);
                acc[t]=fma2(wv.u[1],xv.u[1],acc[t]);
            }
        }
        int slot = (c<RR)? c : (c<RR+NS ? 8+(c-RR) : 24+(c-RR-NS));
#pragma unroll
        for(int t=0;t<8;t++) stage[k*TT+t0+t][slot]=LOF(acc[t])+HIF(acc[t]);
    }
    __syncthreads();

    if (tid < DI){
        int d = tid;
#pragma unroll
        for(int k=0;k<KK;k++){
            float dtw[RR];
#pragma unroll
            for(int r=0;r<RR;r++) dtw[r]=dtw_g[(size_t)(k*DI+d)*RR+r];
            float bias=dtb_g[k*DI+d];
            float A0 = -__expf(alog[(size_t)(k*DI+d)*NS]);
            float2* pb = g_pre + ((size_t)(b*KK+k)*LL)*DI + d;
#pragma unroll 4
            for(int t=0;t<TT;t++){
                int lsp=l0+t;
                int p = (k==0)? lsp : (k==1 ? (lsp%WW)*HH + lsp/WW : LL-1-lsp);
                float s=bias;
#pragma unroll
                for(int r=0;r<RR;r++) s += dtw[r]*stage[k*TT+t][r];
                float dt = fmaxf(s,0.f) + __logf(1.f + __expf(-fabsf(s)));
                float e1 = __expf(dt * A0);
                pb[(size_t)p*DI] = make_float2(e1, dt*sxc[t*DI+d]);
            }
        }
    }

    for(int i=tid; i<KK*TT*XD; i+=256){
        int row=i/XD, j=i%XD;
        int k=row/TT, t=row%TT;
        int lsp=l0+t;
        int p = (k==0)? lsp : (k==1 ? (lsp%WW)*HH + lsp/WW : LL-1-lsp);
        g_xdbl[((size_t)(b*KK+k)*LL+p)*XD + j] = stage[row][8+j];
    }
}

/* tree powers: a[j] = (e1^(2j+1), e1^(2j+2)) */
__device__ __forceinline__ void tree_pow(float e1, u64 a[8]){
    float e2=e1*e1, e4=e2*e2, e8=e4*e4;
    u64 e2p=F2P(e2,e2), e4p=F2P(e4,e4), e8p=F2P(e8,e8);
    a[0]=F2P(e1,e2);
    a[1]=mul2(a[0],e2p);
    a[2]=mul2(a[0],e4p);
    a[3]=mul2(a[1],e4p);
    a[4]=mul2(a[0],e8p);
    a[5]=mul2(a[1],e8p);
    a[6]=mul2(a[2],e8p);
    a[7]=mul2(a[3],e8p);
}

/* one unit-path scan step (states packed in h2[8]) */
__device__ __forceinline__ void scan_step1(float2 ed, const float* sbrow, u64 h2[8]){
    u64 du2=F2P(ed.y,ed.y);
    u64 a[8]; tree_pow(ed.x, a);
    const F4U* bp=reinterpret_cast<const F4U*>(sbrow);
#pragma unroll
    for(int j=0;j<4;j++){
        F4U bv=bp[j];
        h2[2*j]  = fma2(a[2*j],  h2[2*j],  mul2(du2,bv.u[0]));
        h2[2*j+1]= fma2(a[2*j+1],h2[2*j+1],mul2(du2,bv.u[1]));
    }
}

/* ------------- scan pass 1: segment summaries, h0=0 (PF=4 prefetch) ------------- */
__global__ __launch_bounds__(DI, 4) void k_scan1(const float* __restrict__ alog)
{
    __shared__ float sb[LSEG*32];
    int seg = blockIdx.x, bk = blockIdx.y;
    int d = threadIdx.x;
    int chain = bk*DI + d;
    int k = bk % KK;
    int l0 = seg*LSEG;
    {
        const float4* src = reinterpret_cast<const float4*>(g_xdbl + ((size_t)bk*LL + l0)*XD);
        for(int i=threadIdx.x;i<LSEG*8;i+=blockDim.x)
            reinterpret_cast<float4*>(sb)[i]=src[i];
    }
    __syncthreads();

    const float* ar = alog + (size_t)(k*DI+d)*NS;
    float a0 = ar[0];
    bool unit=true;
#pragma unroll
    for(int n=0;n<NS;n++){
        float r=__expf(ar[n]-a0);
        unit = unit && (fabsf(r-(float)(n+1))<1e-3f);
    }
    bool wunit = __all_sync(0xffffffffu, unit);
    const float2* pre = g_pre + (size_t)bk*LL*DI + d;
    float pe=1.f;
    if(wunit){
        u64 h2[8];
#pragma unroll
        for(int j=0;j<8;j++) h2[j]=0ull;
        float2 buf[4];
#pragma unroll
        for(int j=0;j<4;j++) buf[j]=pre[(size_t)(l0+j)*DI];
        for(int io=0;io<LSEG;io+=4){
            float2 nx[4];
            if(io+4<LSEG){
#pragma unroll
                for(int j=0;j<4;j++) nx[j]=pre[(size_t)(l0+io+4+j)*DI];
            }
#pragma unroll
            for(int j=0;j<4;j++){
                pe*=buf[j].x;
                scan_step1(buf[j], &sb[(io+j)*32], h2);
            }
#pragma unroll
            for(int j=0;j<4;j++) buf[j]=nx[j];
        }
#pragma unroll
        for(int j=0;j<8;j++){
            g_segq[seg][2*j][chain]  =LOF(h2[j]);
            g_segq[seg][2*j+1][chain]=HIF(h2[j]);
        }
    } else {
        float rn[NS], h[NS];
#pragma unroll
        for(int n=0;n<NS;n++){ rn[n]=__expf(ar[n]-a0); h[n]=0.f; }
        for(int i=0;i<LSEG;i++){
            float2 ed=pre[(size_t)(l0+i)*DI];
            pe*=ed.x;
            float lg=__log2f(ed.x), du=ed.y;
#pragma unroll
            for(int n=0;n<NS;n++)
                h[n]=exp2f(lg*rn[n])*h[n] + du*sb[i*32+n];
        }
#pragma unroll
        for(int n=0;n<NS;n++) g_segq[seg][n][chain]=h[n];
    }
    g_segp[seg][chain]=pe;
}

/* ------------- combine: two-level parallel prefix (8 threads x 6 segments) ------------- */
__global__ __launch_bounds__(256) void k_comb(const float* __restrict__ alog)
{
    int gt = blockIdx.x*256 + threadIdx.x;   /* CH*NS*8 threads */
    int t  = gt & 7;
    int cn = gt >> 3;
    int chain = cn % CH;
    int n  = cn / CH;
    int d = chain % DI, k = (chain / DI) % KK;
    const float* ar = alog + (size_t)(k*DI+d)*NS;
    float ratio = __expf(ar[n] - ar[0]);
    float rf = rintf(ratio);
    int   m  = (int)rf;
    bool exact = (fabsf(ratio-rf) < 1e-3f) && m >= 1 && m <= 31;
    int s0 = t*6;                            /* 48 = 8 x 6 */
    float A=1.f, Q=0.f;
    float Ap[6], Qp[6];
#pragma unroll
    for(int i=0;i<6;i++){
        Ap[i]=A; Qp[i]=Q;
        float pe = __ldg(&g_segp[s0+i][chain]);
        float q  = __ldg(&g_segq[s0+i][n][chain]);
        float a;
        if (exact){
            float pe2=pe*pe, pe4=pe2*pe2, pe8=pe4*pe4, pe16=pe8*pe8;
            a = (m&1)? pe : 1.f;
            if(m&2)  a*=pe2;
            if(m&4)  a*=pe4;
            if(m&8)  a*=pe8;
            if(m&16) a*=pe16;
        } else {
            a = exp2f(__log2f(pe)*ratio);
        }
        A = a*A;
        Q = a*Q + q;
    }
#pragma unroll
    for(int dlt=1; dlt<8; dlt<<=1){
        float Apv = __shfl_up_sync(0xffffffffu, A, dlt, 8);
        float Qpv = __shfl_up_sync(0xffffffffu, Q, dlt, 8);
        if (t >= dlt){ Q = A*Qpv + Q; A = A*Apv; }
    }
    float hin = __shfl_up_sync(0xffffffffu, Q, 1, 8);
    if (t == 0) hin = 0.f;
#pragma unroll
    for(int i=0;i<6;i++)
        g_hin[s0+i][n][chain] = Ap[i]*hin + Qp[i];
}

/* ------------- scan pass 2: rescan with h_init, emit y (PF=4 prefetch) ------------- */
__global__ __launch_bounds__(DI, 4) void k_scan2(const float* __restrict__ alog)
{
    __shared__ float sb[LSEG*32];
    int seg=blockIdx.x, bk=blockIdx.y;
    int d=threadIdx.x;
    int chain=bk*DI+d;
    int k=bk%KK, b=bk/KK;
    int l0=seg*LSEG;
    {
        const float4* src = reinterpret_cast<const float4*>(g_xdbl + ((size_t)bk*LL + l0)*XD);
        for(int i=threadIdx.x;i<LSEG*8;i+=blockDim.x)
            reinterpret_cast<float4*>(sb)[i]=src[i];
    }
    __syncthreads();
    const float* ar=alog+(size_t)(k*DI+d)*NS;
    float a0=ar[0];
    bool unit=true;
#pragma unroll
    for(int n=0;n<NS;n++){ float r=__expf(ar[n]-a0); unit=unit&&(fabsf(r-(float)(n+1))<1e-3f); }
    bool wunit=__all_sync(0xffffffffu,unit);
    const float2* pre=g_pre+(size_t)bk*LL*DI+d;
    float* yout=g_ys[k]+(size_t)b*LL*DI+d;
    int hh=l0%HH, wc=l0/HH;
    if(wunit){
        u64 h2[8];
#pragma unroll
        for(int j=0;j<8;j++) h2[j]=F2P(g_hin[seg][2*j][chain], g_hin[seg][2*j+1][chain]);
        float2 buf[4];
#pragma unroll
        for(int j=0;j<4;j++) buf[j]=pre[(size_t)(l0+j)*DI];
        for(int io=0;io<LSEG;io+=4){
            float2 nx[4];
            if(io+4<LSEG){
#pragma unroll
                for(int j=0;j<4;j++) nx[j]=pre[(size_t)(l0+io+4+j)*DI];
            }
#pragma unroll
            for(int jj=0;jj<4;jj++){
                float2 ed = buf[jj];
                int i = io + jj;
                u64 du2=F2P(ed.y,ed.y);
                u64 a[8]; tree_pow(ed.x, a);
                const F4U* bp=reinterpret_cast<const F4U*>(&sb[i*32]);
                const F4U* cp=reinterpret_cast<const F4U*>(&sb[i*32+16]);
                u64 ya=0ull, yb=0ull;
#pragma unroll
                for(int j=0;j<4;j++){
                    F4U bv=bp[j]; F4U cv=cp[j];
                    h2[2*j]  =fma2(a[2*j],  h2[2*j],  mul2(du2,bv.u[0])); ya=fma2(h2[2*j],  cv.u[0],ya);
                    h2[2*j+1]=fma2(a[2*j+1],h2[2*j+1],mul2(du2,bv.u[1])); yb=fma2(h2[2*j+1],cv.u[1],yb);
                }
                float y=LOF(ya)+HIF(ya)+LOF(yb)+HIF(yb);
                int l=l0+i, pos;
                if(k==0) pos=l;
                else if(k==1){ pos=hh*WW+wc; hh++; if(hh==HH){hh=0;wc++;} }
                else pos=LL-1-l;
                yout[(size_t)pos*DI]=y;
            }
#pragma unroll
            for(int j=0;j<4;j++) buf[j]=nx[j];
        }
    } else {
        float rn[NS],h[NS];
#pragma unroll
        for(int n=0;n<NS;n++){ rn[n]=__expf(ar[n]-a0); h[n]=g_hin[seg][n][chain]; }
        for(int i=0;i<LSEG;i++){
            float2 ed=pre[(size_t)(l0+i)*DI];
            float lg=__log2f(ed.x), du=ed.y, y=0.f;
#pragma unroll
            for(int n=0;n<NS;n++){
                h[n]=exp2f(lg*rn[n])*h[n]+du*sb[i*32+n];
                y+=h[n]*sb[i*32+16+n];
            }
            int l=l0+i,pos;
            if(k==0)pos=l;
            else if(k==1){pos=hh*WW+wc;hh++;if(hh==HH){hh=0;wc++;}}
            else pos=LL-1-l;
            yout[(size_t)pos*DI]=y;
        }
    }
}

/* ------------- merge (vectorized) + D-term + gating + out_proj ------------- */
__global__ __launch_bounds__(128) void k_out(const float* __restrict__ ow, const float* __restrict__ Ds,
                                             float* __restrict__ out)
{
    __shared__ float yz[16*DI];
    __shared__ float dsum_s[DI];
    int tid=threadIdx.x;
    int tb=blockIdx.x*16;
    size_t base4=(size_t)tb*DI/4;
    for(int i=tid;i<DI;i+=128) dsum_s[i]=Ds[i]+Ds[DI+i]+Ds[2*DI+i];
    __syncthreads();
    {
        const float4* y0=reinterpret_cast<const float4*>(g_ys[0])+base4;
        const float4* y1=reinterpret_cast<const float4*>(g_ys[1])+base4;
        const float4* y2=reinterpret_cast<const float4*>(g_ys[2])+base4;
        const float4* xc=reinterpret_cast<const float4*>(g_xch)+base4;
        const float4* zz=reinterpret_cast<const float4*>(g_z)+base4;
#pragma unroll
        for(int it=0; it<6; it++){
            int i4 = tid + it*128;
            int dd4=(i4*4)%DI;
            float4 a=y0[i4], b=y1[i4], c=y2[i4], x=xc[i4], z=zz[i4];
            float4 ds=*reinterpret_cast<const float4*>(&dsum_s[dd4]);
            float4 v;
            v.x=(a.x+b.x+c.x+ds.x*x.x)*z.x;
            v.y=(a.y+b.y+c.y+ds.y*x.y)*z.y;
            v.z=(a.z+b.z+c.z+ds.z*x.z)*z.z;
            v.w=(a.w+b.w+c.w+ds.w*x.w)*z.w;
            *reinterpret_cast<float4*>(&yz[i4*4])=v;
        }
    }
    __syncthreads();
    int j=tid;
    if(j<DM){
        u64 acc[16];
#pragma unroll
        for(int t=0;t<16;t++) acc[t]=0ull;
        const float4* w4=reinterpret_cast<const float4*>(ow+(size_t)j*DI);
        for(int d4=0;d4<DI/4;d4++){
            F4U wv; wv.f=w4[d4];
#pragma unroll
            for(int t=0;t<16;t++){
                F4U xv; xv.f=*reinterpret_cast<const float4*>(&yz[t*DI+d4*4]);
                acc[t]=fma2(wv.u[0],xv.u[0],acc[t]);
                acc[t]=fma2(wv.u[1],xv.u[1],acc[t]);
            }
        }
#pragma unroll
        for(int t=0;t<16;t++) out[(size_t)(tb+t)*DM+j]=LOF(acc[t])+HIF(acc[t]);
    }
}

/* ---------------- launcher ---------------- */
extern "C" void kernel_launch(void* const* d_in, const int* in_sizes, int n_in,
                              void* d_out, int out_size)
{
    const float* x    = (const float*)d_in[0];
    const float* inw  = (const float*)d_in[2];
    const float* cw   = (const float*)d_in[3];
    const float* cb   = (const float*)d_in[4];
    const float* xw   = (const float*)d_in[5];
    const float* dtw  = (const float*)d_in[6];
    const float* dtb  = (const float*)d_in[7];
    const float* alog = (const float*)d_in[8];
    const float* Ds   = (const float*)d_in[9];
    const float* ow   = (const float*)d_in[10];
    float* out = (float*)d_out;

    k_inproj<<<BB*LL/16, 384>>>(x, inw);
    k_mid   <<<dim3(LL/TT, BB), 256>>>(cw, cb, xw, dtw, dtb, alog);
    k_scan1 <<<dim3(SS, BB*KK), DI>>>(alog);
    k_comb  <<<CH*NS*8/256, 256>>>(alog);
    k_scan2 <<<dim3(SS, BB*KK), DI>>>(alog);
    k_out   <<<BB*LL/16, 128>>>(ow, Ds, out);
}

// round 15
// speedup vs baseline: 1.1034x; 1.0113x over previous
#include <cuda_runtime.h>
#include <math.h>

#define BB 4
#define HH 48
#define WW 48
#define LL (HH*WW)      /* 2304 */
#define DM 96
#define DI 192
#define NS 16
#define RR 6
#define KK 3
#define XD 32           /* row: [B0..B15, C0..C15] */
#define CH (BB*KK*DI)   /* 2304 chains */
#define SS 48           /* scan segments */
#define LSEG (LL/SS)    /* 48 */
#define TT 16           /* spatial tokens per k_mid block */
#define PF 6            /* scan prefetch depth */

typedef unsigned long long u64;
union F2U { float2 f; u64 u; };
union F4U { float4 f; u64 u[2]; };

__device__ __forceinline__ u64 F2P(float x, float y){ F2U t; t.f=make_float2(x,y); return t.u; }
__device__ __forceinline__ float LOF(u64 v){ F2U t; t.u=v; return t.f.x; }
__device__ __forceinline__ float HIF(u64 v){ F2U t; t.u=v; return t.f.y; }
__device__ __forceinline__ u64 fma2(u64 a,u64 b,u64 c){ u64 d; asm("fma.rn.f32x2 %0,%1,%2,%3;":"=l"(d):"l"(a),"l"(b),"l"(c)); return d; }
__device__ __forceinline__ u64 mul2(u64 a,u64 b){ u64 d; asm("mul.rn.f32x2 %0,%1,%2;":"=l"(d):"l"(a),"l"(b)); return d; }

/* ---------------- scratch ---------------- */
__device__ float  g_xcraw[BB*LL*DI];
__device__ float  g_z    [BB*LL*DI];
__device__ float  g_xch  [BB*LL*DI];
__device__ float  g_xdbl [BB*KK*LL*XD];
__device__ float2 g_pre  [(size_t)BB*KK*LL*DI];   /* {e1, dt*u}  [bk][l][d] */
__device__ float  g_segq [SS][NS][CH];
__device__ float  g_segp [SS][CH];
__device__ float  g_hin  [SS][NS][CH];
__device__ float  g_ys   [KK][BB*LL*DI];

__device__ __forceinline__ float fsilu(float v){ return v / (1.f + __expf(-v)); }

/* ------------- in_proj ------------- */
__global__ void k_inproj(const float* __restrict__ x, const float* __restrict__ w)
{
    __shared__ float xt[16*DM];
    int tb = blockIdx.x * 16;
    for (int i=threadIdx.x;i<16*DM;i+=blockDim.x) xt[i]=x[(size_t)tb*DM+i];
    __syncthreads();
    int j = threadIdx.x;
    u64 acc[16];
#pragma unroll
    for(int t=0;t<16;t++) acc[t]=0ull;
    const float4* w4 = reinterpret_cast<const float4*>(w + j*DM);
#pragma unroll
    for(int c4=0;c4<DM/4;c4++){
        F4U wv; wv.f = w4[c4];
#pragma unroll
        for(int t=0;t<16;t++){
            F4U xv; xv.f = *reinterpret_cast<const float4*>(&xt[t*DM+c4*4]);
            acc[t]=fma2(wv.u[0],xv.u[0],acc[t]);
            acc[t]=fma2(wv.u[1],xv.u[1],acc[t]);
        }
    }
    if(j<DI){
#pragma unroll
        for(int t=0;t<16;t++) g_xcraw[(size_t)(tb+t)*DI+j]=LOF(acc[t])+HIF(acc[t]);
    } else {
        int jz=j-DI;
#pragma unroll
        for(int t=0;t<16;t++) g_z[(size_t)(tb+t)*DI+jz]=fsilu(LOF(acc[t])+HIF(acc[t]));
    }
}

/* ------------- fused conv + x_proj + dt_proj + delta (TT=16 tile) ------------- */
__global__ __launch_bounds__(256) void k_mid(
    const float* __restrict__ cw, const float* __restrict__ cb,
    const float* __restrict__ xw,
    const float* __restrict__ dtw_g, const float* __restrict__ dtb_g,
    const float* __restrict__ alog)
{
    __shared__ float sxc[TT*DI];
    __shared__ float stage[KK*TT][40];
    int b  = blockIdx.y;
    int l0 = blockIdx.x * TT;
    int tid = threadIdx.x;

    if (tid < DI){
        int d = tid;
        float wt[9];
#pragma unroll
        for(int i=0;i<9;i++) wt[i]=cw[d*9+i];
        float bias=cb[d];
        const float* base = g_xcraw + (size_t)b*LL*DI + d;
        float* xo = g_xch + ((size_t)b*LL + l0)*DI + d;
#pragma unroll 4
        for(int t=0;t<TT;t++){
            int l=l0+t, h=l/WW, w0=l%WW;
            float s=bias;
#pragma unroll
            for(int kh=0;kh<3;kh++){
                int h2=h+kh-1;
                if((unsigned)h2>=HH) continue;
#pragma unroll
                for(int kw=0;kw<3;kw++){
                    int w2=w0+kw-1;
                    if((unsigned)w2>=WW) continue;
                    s += base[(size_t)(h2*WW+w2)*DI]*wt[kh*3+kw];
                }
            }
            float v=fsilu(s);
            sxc[t*DI+d]=v;
            xo[(size_t)t*DI]=v;
        }
    }
    __syncthreads();

    if (tid < 228){
        int j = tid % 114;
        int t0 = (tid >= 114) ? 8 : 0;
        int k = j/38, c = j%38;
        u64 acc[8];
#pragma unroll
        for(int t=0;t<8;t++) acc[t]=0ull;
        const float4* w4 = reinterpret_cast<const float4*>(xw + (size_t)(k*38+c)*DI);
        for(int d4=0; d4<DI/4; d4++){
            F4U wv; wv.f=w4[d4];
#pragma unroll
            for(int t=0;t<8;t++){
                F4U xv; xv.f=*reinterpret_cast<const float4*>(&sxc[(t0+t)*DI+d4*4]);
                acc[t]=fma2(wv.u[0],xv.u[0],acc[t]);
                acc[t]=fma2(wv.u[1],xv.u[1],acc[t]);
            }
        }
        int slot = (c<RR)? c : (c<RR+NS ? 8+(c-RR) : 24+(c-RR-NS));
#pragma unroll
        for(int t=0;t<8;t++) stage[k*TT+t0+t][slot]=LOF(acc[t])+HIF(acc[t]);
    }
    __syncthreads();

    if (tid < DI){
        int d = tid;
#pragma unroll
        for(int k=0;k<KK;k++){
            float dtw[RR];
#pragma unroll
            for(int r=0;r<RR;r++) dtw[r]=dtw_g[(size_t)(k*DI+d)*RR+r];
            float bias=dtb_g[k*DI+d];
            float A0 = -__expf(alog[(size_t)(k*DI+d)*NS]);
            float2* pb = g_pre + ((size_t)(b*KK+k)*LL)*DI + d;
#pragma unroll 4
            for(int t=0;t<TT;t++){
                int lsp=l0+t;
                int p = (k==0)? lsp : (k==1 ? (lsp%WW)*HH + lsp/WW : LL-1-lsp);
                float s=bias;
#pragma unroll
                for(int r=0;r<RR;r++) s += dtw[r]*stage[k*TT+t][r];
                float dt = fmaxf(s,0.f) + __logf(1.f + __expf(-fabsf(s)));
                float e1 = __expf(dt * A0);
                pb[(size_t)p*DI] = make_float2(e1, dt*sxc[t*DI+d]);
            }
        }
    }

    for(int i=tid; i<KK*TT*XD; i+=256){
        int row=i/XD, j=i%XD;
        int k=row/TT, t=row%TT;
        int lsp=l0+t;
        int p = (k==0)? lsp : (k==1 ? (lsp%WW)*HH + lsp/WW : LL-1-lsp);
        g_xdbl[((size_t)(b*KK+k)*LL+p)*XD + j] = stage[row][8+j];
    }
}

/* tree powers: a[j] = (e1^(2j+1), e1^(2j+2)) */
__device__ __forceinline__ void tree_pow(float e1, u64 a[8]){
    float e2=e1*e1, e4=e2*e2, e8=e4*e4;
    u64 e2p=F2P(e2,e2), e4p=F2P(e4,e4), e8p=F2P(e8,e8);
    a[0]=F2P(e1,e2);
    a[1]=mul2(a[0],e2p);
    a[2]=mul2(a[0],e4p);
    a[3]=mul2(a[1],e4p);
    a[4]=mul2(a[0],e8p);
    a[5]=mul2(a[1],e8p);
    a[6]=mul2(a[2],e8p);
    a[7]=mul2(a[3],e8p);
}

/* one unit-path scan step (states packed in h2[8]) */
__device__ __forceinline__ void scan_step1(float2 ed, const float* sbrow, u64 h2[8]){
    u64 du2=F2P(ed.y,ed.y);
    u64 a[8]; tree_pow(ed.x, a);
    const F4U* bp=reinterpret_cast<const F4U*>(sbrow);
#pragma unroll
    for(int j=0;j<4;j++){
        F4U bv=bp[j];
        h2[2*j]  = fma2(a[2*j],  h2[2*j],  mul2(du2,bv.u[0]));
        h2[2*j+1]= fma2(a[2*j+1],h2[2*j+1],mul2(du2,bv.u[1]));
    }
}

/* ------------- scan pass 1: segment summaries, h0=0 (PF=6, B-only staging) ------------- */
__global__ __launch_bounds__(DI, 4) void k_scan1(const float* __restrict__ alog)
{
    __shared__ float sb[LSEG*16];   /* B half only */
    int seg = blockIdx.x, bk = blockIdx.y;
    int d = threadIdx.x;
    int chain = bk*DI + d;
    int k = bk % KK;
    int l0 = seg*LSEG;
    {
        const float4* src = reinterpret_cast<const float4*>(g_xdbl + ((size_t)bk*LL + l0)*XD);
        for(int i=threadIdx.x;i<LSEG*4;i+=blockDim.x){
            int row=i>>2, q=i&3;
            reinterpret_cast<float4*>(sb)[i]=src[row*8+q];
        }
    }
    __syncthreads();

    const float* ar = alog + (size_t)(k*DI+d)*NS;
    float a0 = ar[0];
    bool unit=true;
#pragma unroll
    for(int n=0;n<NS;n++){
        float r=__expf(ar[n]-a0);
        unit = unit && (fabsf(r-(float)(n+1))<1e-3f);
    }
    bool wunit = __all_sync(0xffffffffu, unit);
    const float2* pre = g_pre + (size_t)bk*LL*DI + d;
    float pe=1.f;
    if(wunit){
        u64 h2[8];
#pragma unroll
        for(int j=0;j<8;j++) h2[j]=0ull;
        float2 buf[PF];
#pragma unroll
        for(int j=0;j<PF;j++) buf[j]=pre[(size_t)(l0+j)*DI];
        for(int io=0;io<LSEG;io+=PF){
            float2 nx[PF];
            if(io+PF<LSEG){
#pragma unroll
                for(int j=0;j<PF;j++) nx[j]=pre[(size_t)(l0+io+PF+j)*DI];
            }
#pragma unroll
            for(int j=0;j<PF;j++){
                pe*=buf[j].x;
                scan_step1(buf[j], &sb[(io+j)*16], h2);
            }
#pragma unroll
            for(int j=0;j<PF;j++) buf[j]=nx[j];
        }
#pragma unroll
        for(int j=0;j<8;j++){
            g_segq[seg][2*j][chain]  =LOF(h2[j]);
            g_segq[seg][2*j+1][chain]=HIF(h2[j]);
        }
    } else {
        float rn[NS], h[NS];
#pragma unroll
        for(int n=0;n<NS;n++){ rn[n]=__expf(ar[n]-a0); h[n]=0.f; }
        for(int i=0;i<LSEG;i++){
            float2 ed=pre[(size_t)(l0+i)*DI];
            pe*=ed.x;
            float lg=__log2f(ed.x), du=ed.y;
#pragma unroll
            for(int n=0;n<NS;n++)
                h[n]=exp2f(lg*rn[n])*h[n] + du*sb[i*16+n];
        }
#pragma unroll
        for(int n=0;n<NS;n++) g_segq[seg][n][chain]=h[n];
    }
    g_segp[seg][chain]=pe;
}

/* ------------- combine: two-level parallel prefix (8 threads x 6 segments) ------------- */
__global__ __launch_bounds__(256) void k_comb(const float* __restrict__ alog)
{
    int gt = blockIdx.x*256 + threadIdx.x;   /* CH*NS*8 threads */
    int t  = gt & 7;
    int cn = gt >> 3;
    int chain = cn % CH;
    int n  = cn / CH;
    int d = chain % DI, k = (chain / DI) % KK;
    const float* ar = alog + (size_t)(k*DI+d)*NS;
    float ratio = __expf(ar[n] - ar[0]);
    float rf = rintf(ratio);
    int   m  = (int)rf;
    bool exact = (fabsf(ratio-rf) < 1e-3f) && m >= 1 && m <= 31;
    int s0 = t*6;                            /* 48 = 8 x 6 */
    float A=1.f, Q=0.f;
    float Ap[6], Qp[6];
#pragma unroll
    for(int i=0;i<6;i++){
        Ap[i]=A; Qp[i]=Q;
        float pe = __ldg(&g_segp[s0+i][chain]);
        float q  = __ldg(&g_segq[s0+i][n][chain]);
        float a;
        if (exact){
            float pe2=pe*pe, pe4=pe2*pe2, pe8=pe4*pe4, pe16=pe8*pe8;
            a = (m&1)? pe : 1.f;
            if(m&2)  a*=pe2;
            if(m&4)  a*=pe4;
            if(m&8)  a*=pe8;
            if(m&16) a*=pe16;
        } else {
            a = exp2f(__log2f(pe)*ratio);
        }
        A = a*A;
        Q = a*Q + q;
    }
#pragma unroll
    for(int dlt=1; dlt<8; dlt<<=1){
        float Apv = __shfl_up_sync(0xffffffffu, A, dlt, 8);
        float Qpv = __shfl_up_sync(0xffffffffu, Q, dlt, 8);
        if (t >= dlt){ Q = A*Qpv + Q; A = A*Apv; }
    }
    float hin = __shfl_up_sync(0xffffffffu, Q, 1, 8);
    if (t == 0) hin = 0.f;
#pragma unroll
    for(int i=0;i<6;i++)
        g_hin[s0+i][n][chain] = Ap[i]*hin + Qp[i];
}

/* ------------- scan pass 2: rescan with h_init, emit y (PF=6) ------------- */
__global__ __launch_bounds__(DI, 4) void k_scan2(const float* __restrict__ alog)
{
    __shared__ float sb[LSEG*32];
    int seg=blockIdx.x, bk=blockIdx.y;
    int d=threadIdx.x;
    int chain=bk*DI+d;
    int k=bk%KK, b=bk/KK;
    int l0=seg*LSEG;
    {
        const float4* src = reinterpret_cast<const float4*>(g_xdbl + ((size_t)bk*LL + l0)*XD);
        for(int i=threadIdx.x;i<LSEG*8;i+=blockDim.x)
            reinterpret_cast<float4*>(sb)[i]=src[i];
    }
    __syncthreads();
    const float* ar=alog+(size_t)(k*DI+d)*NS;
    float a0=ar[0];
    bool unit=true;
#pragma unroll
    for(int n=0;n<NS;n++){ float r=__expf(ar[n]-a0); unit=unit&&(fabsf(r-(float)(n+1))<1e-3f); }
    bool wunit=__all_sync(0xffffffffu,unit);
    const float2* pre=g_pre+(size_t)bk*LL*DI+d;
    float* yout=g_ys[k]+(size_t)b*LL*DI+d;
    int hh=l0%HH, wc=l0/HH;
    if(wunit){
        u64 h2[8];
#pragma unroll
        for(int j=0;j<8;j++) h2[j]=F2P(g_hin[seg][2*j][chain], g_hin[seg][2*j+1][chain]);
        float2 buf[PF];
#pragma unroll
        for(int j=0;j<PF;j++) buf[j]=pre[(size_t)(l0+j)*DI];
        for(int io=0;io<LSEG;io+=PF){
            float2 nx[PF];
            if(io+PF<LSEG){
#pragma unroll
                for(int j=0;j<PF;j++) nx[j]=pre[(size_t)(l0+io+PF+j)*DI];
            }
#pragma unroll
            for(int jj=0;jj<PF;jj++){
                float2 ed = buf[jj];
                int i = io + jj;
                u64 du2=F2P(ed.y,ed.y);
                u64 a[8]; tree_pow(ed.x, a);
                const F4U* bp=reinterpret_cast<const F4U*>(&sb[i*32]);
                const F4U* cp=reinterpret_cast<const F4U*>(&sb[i*32+16]);
                u64 ya=0ull, yb=0ull;
#pragma unroll
                for(int j=0;j<4;j++){
                    F4U bv=bp[j]; F4U cv=cp[j];
                    h2[2*j]  =fma2(a[2*j],  h2[2*j],  mul2(du2,bv.u[0])); ya=fma2(h2[2*j],  cv.u[0],ya);
                    h2[2*j+1]=fma2(a[2*j+1],h2[2*j+1],mul2(du2,bv.u[1])); yb=fma2(h2[2*j+1],cv.u[1],yb);
                }
                float y=LOF(ya)+HIF(ya)+LOF(yb)+HIF(yb);
                int l=l0+i, pos;
                if(k==0) pos=l;
                else if(k==1){ pos=hh*WW+wc; hh++; if(hh==HH){hh=0;wc++;} }
                else pos=LL-1-l;
                yout[(size_t)pos*DI]=y;
            }
#pragma unroll
            for(int j=0;j<PF;j++) buf[j]=nx[j];
        }
    } else {
        float rn[NS],h[NS];
#pragma unroll
        for(int n=0;n<NS;n++){ rn[n]=__expf(ar[n]-a0); h[n]=g_hin[seg][n][chain]; }
        for(int i=0;i<LSEG;i++){
            float2 ed=pre[(size_t)(l0+i)*DI];
            float lg=__log2f(ed.x), du=ed.y, y=0.f;
#pragma unroll
            for(int n=0;n<NS;n++){
                h[n]=exp2f(lg*rn[n])*h[n]+du*sb[i*32+n];
                y+=h[n]*sb[i*32+16+n];
            }
            int l=l0+i,pos;
            if(k==0)pos=l;
            else if(k==1){pos=hh*WW+wc;hh++;if(hh==HH){hh=0;wc++;}}
            else pos=LL-1-l;
            yout[(size_t)pos*DI]=y;
        }
    }
}

/* ------------- merge (vectorized) + D-term + gating + out_proj ------------- */
__global__ __launch_bounds__(128) void k_out(const float* __restrict__ ow, const float* __restrict__ Ds,
                                             float* __restrict__ out)
{
    __shared__ float yz[16*DI];
    __shared__ float dsum_s[DI];
    int tid=threadIdx.x;
    int tb=blockIdx.x*16;
    size_t base4=(size_t)tb*DI/4;
    for(int i=tid;i<DI;i+=128) dsum_s[i]=Ds[i]+Ds[DI+i]+Ds[2*DI+i];
    __syncthreads();
    {
        const float4* y0=reinterpret_cast<const float4*>(g_ys[0])+base4;
        const float4* y1=reinterpret_cast<const float4*>(g_ys[1])+base4;
        const float4* y2=reinterpret_cast<const float4*>(g_ys[2])+base4;
        const float4* xc=reinterpret_cast<const float4*>(g_xch)+base4;
        const float4* zz=reinterpret_cast<const float4*>(g_z)+base4;
#pragma unroll
        for(int it=0; it<6; it++){
            int i4 = tid + it*128;
            int dd4=(i4*4)%DI;
            float4 a=y0[i4], b=y1[i4], c=y2[i4], x=xc[i4], z=zz[i4];
            float4 ds=*reinterpret_cast<const float4*>(&dsum_s[dd4]);
            float4 v;
            v.x=(a.x+b.x+c.x+ds.x*x.x)*z.x;
            v.y=(a.y+b.y+c.y+ds.y*x.y)*z.y;
            v.z=(a.z+b.z+c.z+ds.z*x.z)*z.z;
            v.w=(a.w+b.w+c.w+ds.w*x.w)*z.w;
            *reinterpret_cast<float4*>(&yz[i4*4])=v;
        }
    }
    __syncthreads();
    int j=tid;
    if(j<DM){
        u64 acc[16];
#pragma unroll
        for(int t=0;t<16;t++) acc[t]=0ull;
        const float4* w4=reinterpret_cast<const float4*>(ow+(size_t)j*DI);
        for(int d4=0;d4<DI/4;d4++){
            F4U wv; wv.f=w4[d4];
#pragma unroll
            for(int t=0;t<16;t++){
                F4U xv; xv.f=*reinterpret_cast<const float4*>(&yz[t*DI+d4*4]);
                acc[t]=fma2(wv.u[0],xv.u[0],acc[t]);
                acc[t]=fma2(wv.u[1],xv.u[1],acc[t]);
            }
        }
#pragma unroll
        for(int t=0;t<16;t++) out[(size_t)(tb+t)*DM+j]=LOF(acc[t])+HIF(acc[t]);
    }
}

/* ---------------- launcher ---------------- */
extern "C" void kernel_launch(void* const* d_in, const int* in_sizes, int n_in,
                              void* d_out, int out_size)
{
    const float* x    = (const float*)d_in[0];
    const float* inw  = (const float*)d_in[2];
    const float* cw   = (const float*)d_in[3];
    const float* cb   = (const float*)d_in[4];
    const float* xw   = (const float*)d_in[5];
    const float* dtw  = (const float*)d_in[6];
    const float* dtb  = (const float*)d_in[7];
    const float* alog = (const float*)d_in[8];
    const float* Ds   = (const float*)d_in[9];
    const float* ow   = (const float*)d_in[10];
    float* out = (float*)d_out;

    k_inproj<<<BB*LL/16, 384>>>(x, inw);
    k_mid   <<<dim3(LL/TT, BB), 256>>>(cw, cb, xw, dtw, dtb, alog);
    k_scan1 <<<dim3(SS, BB*KK), DI>>>(alog);
    k_comb  <<<CH*NS*8/256, 256>>>(alog);
    k_scan2 <<<dim3(SS, BB*KK), DI>>>(alog);
    k_out   <<<BB*LL/16, 128>>>(ow, Ds, out);
}